// round 5
// baseline (speedup 1.0000x reference)
#include <cuda_runtime.h>
#include <cstdint>

// Problem constants
constexpr int Bsz = 4;
constexpr int Sq  = 2048;
constexpr int Dm  = 1024;

// Scratch (device globals; no allocation allowed)
__device__ float g_X  [(long)Bsz * Sq * Dm];   // tf32-rounded, perm-K layout
__device__ float g_WqT[(long)Dm * Dm];         // rounded + transposed + perm-K
__device__ float g_WkT[(long)Dm * Dm];
__device__ float g_WvT[(long)Dm * Dm];
__device__ float g_Q  [(long)Bsz * Sq * Dm];   // perm-K
__device__ float g_K  [(long)Bsz * Sq * Dm];   // perm-K
__device__ float g_V  [(long)Bsz * Sq * Dm];   // normal
__device__ float g_Vt [(long)Bsz * Sq * Dm];   // V^T per batch, perm-K
__device__ float g_P  [(long)Bsz * Sq * Sq];   // scores->probs, perm-K

// ---------------------------------------------------------------------------
// helpers
// ---------------------------------------------------------------------------
__device__ __forceinline__ uint32_t f2tf32(float f) {
    uint32_t r;
    asm("cvt.rna.tf32.f32 %0, %1;" : "=r"(r) : "f"(f));
    return r;
}
__device__ __forceinline__ float roundtf(float f) { return __uint_as_float(f2tf32(f)); }

__device__ __forceinline__ void cp16(void* s, const void* g) {
    uint32_t sa = (uint32_t)__cvta_generic_to_shared(s);
    asm volatile("cp.async.cg.shared.global [%0], [%1], 16;\n" :: "r"(sa), "l"(g));
}

__device__ __forceinline__ void mma_tf32(float* d, const float4& alo, const float4& ahi,
                                         float bx, float by) {
    asm volatile(
        "mma.sync.aligned.m16n8k8.row.col.f32.tf32.tf32.f32 "
        "{%0,%1,%2,%3},{%4,%5,%6,%7},{%8,%9},{%0,%1,%2,%3};"
        : "+f"(d[0]), "+f"(d[1]), "+f"(d[2]), "+f"(d[3])
        : "r"(__float_as_uint(alo.x)), "r"(__float_as_uint(ahi.x)),
          "r"(__float_as_uint(alo.y)), "r"(__float_as_uint(ahi.y)),
          "r"(__float_as_uint(bx)),    "r"(__float_as_uint(by)));
}
__device__ __forceinline__ void mma_tf32_hi(float* d, const float4& alo, const float4& ahi,
                                            float bx, float by) {
    asm volatile(
        "mma.sync.aligned.m16n8k8.row.col.f32.tf32.tf32.f32 "
        "{%0,%1,%2,%3},{%4,%5,%6,%7},{%8,%9},{%0,%1,%2,%3};"
        : "+f"(d[0]), "+f"(d[1]), "+f"(d[2]), "+f"(d[3])
        : "r"(__float_as_uint(alo.z)), "r"(__float_as_uint(ahi.z)),
          "r"(__float_as_uint(alo.w)), "r"(__float_as_uint(ahi.w)),
          "r"(__float_as_uint(bx)),    "r"(__float_as_uint(by)));
}

__device__ __forceinline__ float warp_max(float v) {
    #pragma unroll
    for (int o = 16; o; o >>= 1) v = fmaxf(v, __shfl_xor_sync(0xFFFFFFFFu, v, o));
    return v;
}
__device__ __forceinline__ float warp_sum(float v) {
    #pragma unroll
    for (int o = 16; o; o >>= 1) v += __shfl_xor_sync(0xFFFFFFFFu, v, o);
    return v;
}

// digit-swap permutation within each 16-element block (involution)
__device__ __forceinline__ int perm16(int j) {
    return (j & ~15) | ((j & 3) << 2) | ((j >> 2) & 3);
}

// ---------------------------------------------------------------------------
// Round to tf32 + permute each 16-float block (4x4 in-block transpose).
// ---------------------------------------------------------------------------
__global__ void __launch_bounds__(256)
roundperm_k(const float* __restrict__ in, float* __restrict__ out, int nblk)
{
    int i = blockIdx.x * blockDim.x + threadIdx.x;
    const int stride = gridDim.x * blockDim.x;
    for (; i < nblk; i += stride) {
        const float4* s = (const float4*)(in + (long)i * 16);
        float4* d = (float4*)(out + (long)i * 16);
        float4 a0 = s[0], a1 = s[1], a2 = s[2], a3 = s[3];
        d[0] = make_float4(roundtf(a0.x), roundtf(a1.x), roundtf(a2.x), roundtf(a3.x));
        d[1] = make_float4(roundtf(a0.y), roundtf(a1.y), roundtf(a2.y), roundtf(a3.y));
        d[2] = make_float4(roundtf(a0.z), roundtf(a1.z), roundtf(a2.z), roundtf(a3.z));
        d[3] = make_float4(roundtf(a0.w), roundtf(a1.w), roundtf(a2.w), roundtf(a3.w));
    }
}

// ---------------------------------------------------------------------------
// Batched 32x32 tile transpose with tf32 round + perm-K output columns.
// out[b][c][perm(r)] = round(in[b][r][c])
// ---------------------------------------------------------------------------
__global__ void __launch_bounds__(256)
transposeperm_k(const float* __restrict__ in, float* __restrict__ out, int R, int Cc)
{
    __shared__ float t[32][33];
    const long bo = (long)blockIdx.z * R * Cc;
    in += bo; out += bo;
    const int r0 = blockIdx.x * 32, c0 = blockIdx.y * 32;
    const int x = threadIdx.x, y = threadIdx.y;   // block (32, 8)
    #pragma unroll
    for (int i = 0; i < 32; i += 8)
        t[y + i][x] = roundtf(in[(long)(r0 + y + i) * Cc + c0 + x]);
    __syncthreads();
    const int px = (x & 16) | ((x & 3) << 2) | ((x >> 2) & 3);
    #pragma unroll
    for (int i = 0; i < 32; i += 8)
        out[(long)(c0 + y + i) * R + r0 + px] = t[x][y + i];
}

// ---------------------------------------------------------------------------
// TF32 mma.sync GEMM on perm-K operands:  C[M,N] = A[M,K] * B[N,K]^T
// CTA tile 64x128, K-chunk 16, 256 threads (8 warps 2x4), warp 32x32.
// 4-stage cp.async pipeline: 3 K-chunks of latency coverage per load.
// Per K16 chunk per warp: 8 LDS.128 + 16 HMMA (zero cvt).
// ---------------------------------------------------------------------------
template <bool CAUSAL_SKIP, bool KLIMIT, bool PERM_OUT, bool ROUND_OUT>
__global__ void __launch_bounds__(256, 2)
mma_gemm(const float* __restrict__ A, const float* __restrict__ Bm,
         float* __restrict__ C,
         int K, int lda, int ldb, int ldc, long sA, long sB, long sC)
{
    const int m0 = blockIdx.y * 64;
    const int n0 = blockIdx.x * 128;
    if (CAUSAL_SKIP && n0 > m0 + 63) return;

    A  += (long)blockIdx.z * sA;
    Bm += (long)blockIdx.z * sB;
    C  += (long)blockIdx.z * sC;

    const int Keff = KLIMIT ? min(K, (m0 + 64 + 127) & ~127) : K;
    const int nkt  = Keff >> 4;

    __shared__ __align__(16) float As[4][64 * 16];
    __shared__ __align__(16) float Bs[4][128 * 16];

    const int tid  = threadIdx.x;
    const int warp = tid >> 5;
    const int lane = tid & 31;
    const int wm   = warp >> 2;     // 0..1
    const int wn   = warp & 3;      // 0..3
    const int q    = lane & 3;
    const int lg   = lane >> 2;

    // per-thread load coords (hoisted)
    const int lar = tid >> 2, lag = tid & 3;
    const float* Abase = A + (long)(m0 + lar) * lda + lag * 4;
    const float* Bbase0 = Bm + (long)(n0 + (tid >> 2)) * ldb + (tid & 3) * 4;
    const float* Bbase1 = Bm + (long)(n0 + ((tid + 256) >> 2)) * ldb + (tid & 3) * 4;

    auto load_stage = [&](int st, int kt) {
        const int k0 = kt << 4;
        cp16(&As[st][lar * 16 + lag * 4], Abase + k0);
        cp16(&Bs[st][(tid >> 2) * 16 + (tid & 3) * 4], Bbase0 + k0);
        cp16(&Bs[st][((tid + 256) >> 2) * 16 + (tid & 3) * 4], Bbase1 + k0);
    };

    // Prologue: 3 stages in flight (always commit so group count is uniform)
    #pragma unroll
    for (int s = 0; s < 3; s++) {
        if (s < nkt) load_stage(s, s);
        asm volatile("cp.async.commit_group;\n");
    }

    float acc[2][4][4] = {};

    for (int kt = 0; kt < nkt; ++kt) {
        const int cur = kt & 3;
        asm volatile("cp.async.wait_group 2;\n");
        __syncthreads();

        // issue next load ASAP (before compute), into the slot freed last iter
        if (kt + 3 < nkt) load_stage((kt + 3) & 3, kt + 3);
        asm volatile("cp.async.commit_group;\n");

        const float4* Af = (const float4*)As[cur];
        const float4* Bf = (const float4*)Bs[cur];

        float4 alo[2], ahi[2], bv[4];
        #pragma unroll
        for (int mi = 0; mi < 2; mi++) {
            const int row = wm * 32 + mi * 16 + lg;
            alo[mi] = Af[row * 4 + q];
            ahi[mi] = Af[(row + 8) * 4 + q];
        }
        #pragma unroll
        for (int ni = 0; ni < 4; ni++) {
            const int nb = wn * 32 + ni * 8 + lg;
            bv[ni] = Bf[nb * 4 + q];
        }
        #pragma unroll
        for (int mi = 0; mi < 2; mi++)
            #pragma unroll
            for (int ni = 0; ni < 4; ni++) {
                mma_tf32   (acc[mi][ni], alo[mi], ahi[mi], bv[ni].x, bv[ni].y);
                mma_tf32_hi(acc[mi][ni], alo[mi], ahi[mi], bv[ni].z, bv[ni].w);
            }
        __syncthreads();
    }

    // Epilogue
    #pragma unroll
    for (int mi = 0; mi < 2; mi++) {
        #pragma unroll
        for (int ni = 0; ni < 4; ni++) {
            const int r0 = m0 + wm * 32 + mi * 16 + lg;
            const int c0 = n0 + wn * 32 + ni * 8 + 2 * q;
            float v0 = acc[mi][ni][0], v1 = acc[mi][ni][1];
            float v2 = acc[mi][ni][2], v3 = acc[mi][ni][3];
            if (ROUND_OUT) { v0 = roundtf(v0); v1 = roundtf(v1);
                             v2 = roundtf(v2); v3 = roundtf(v3); }
            if (PERM_OUT) {
                const int p0 = perm16(c0), p1 = perm16(c0 + 1);
                C[(long)r0 * ldc + p0]       = v0;
                C[(long)r0 * ldc + p1]       = v1;
                C[(long)(r0 + 8) * ldc + p0] = v2;
                C[(long)(r0 + 8) * ldc + p1] = v3;
            } else {
                *(float2*)&C[(long)r0 * ldc + c0]       = make_float2(v0, v1);
                *(float2*)&C[(long)(r0 + 8) * ldc + c0] = make_float2(v2, v3);
            }
        }
    }
}

// ---------------------------------------------------------------------------
// In-place causal row softmax on perm-K P, logits s/32, tf32-rounded output.
// ---------------------------------------------------------------------------
__global__ void __launch_bounds__(256)
softmax_k(float* __restrict__ P)
{
    const int row = blockIdx.x;
    const int b = row >> 11;
    const int i = row & 2047;
    float* p = P + ((long)b * Sq + i) * Sq;
    const int tid = threadIdx.x;
    const int len = i + 1;
    const int lenPad = (len + 127) & ~127;

    float v[8];
    int cnt = 0;
    for (int jp = tid; jp < lenPad; jp += 256) {
        const float raw = p[jp];
        v[cnt++] = (perm16(jp) < len) ? raw : -3.4e38f;
    }

    float mx = -3.4e38f;
    #pragma unroll
    for (int c = 0; c < 8; c++) if (c < cnt) mx = fmaxf(mx, v[c]);
    mx = warp_max(mx);

    __shared__ float red[8];
    if ((tid & 31) == 0) red[tid >> 5] = mx;
    __syncthreads();
    mx = red[0];
    #pragma unroll
    for (int w = 1; w < 8; w++) mx = fmaxf(mx, red[w]);

    float s = 0.f;
    #pragma unroll
    for (int c = 0; c < 8; c++) {
        if (c < cnt) { v[c] = __expf((v[c] - mx) * 0.03125f); s += v[c]; }
    }
    s = warp_sum(s);
    __syncthreads();
    if ((tid & 31) == 0) red[tid >> 5] = s;
    __syncthreads();
    float tot = 0.f;
    #pragma unroll
    for (int w = 0; w < 8; w++) tot += red[w];
    const float inv = 1.0f / tot;

    cnt = 0;
    for (int jp = tid; jp < lenPad; jp += 256)
        p[jp] = roundtf(v[cnt++] * inv);
}

// ---------------------------------------------------------------------------
extern "C" void kernel_launch(void* const* d_in, const int* in_sizes, int n_in,
                              void* d_out, int out_size)
{
    const float* x  = (const float*)d_in[0];
    const float* Wq = (const float*)d_in[1];
    const float* Wk = (const float*)d_in[2];
    const float* Wv = (const float*)d_in[3];
    float* out = (float*)d_out;

    float *X, *WqT, *WkT, *WvT, *Q, *K, *V, *Vt, *P;
    cudaGetSymbolAddress((void**)&X,   g_X);
    cudaGetSymbolAddress((void**)&WqT, g_WqT);
    cudaGetSymbolAddress((void**)&WkT, g_WkT);
    cudaGetSymbolAddress((void**)&WvT, g_WvT);
    cudaGetSymbolAddress((void**)&Q,   g_Q);
    cudaGetSymbolAddress((void**)&K,   g_K);
    cudaGetSymbolAddress((void**)&V,   g_V);
    cudaGetSymbolAddress((void**)&Vt,  g_Vt);
    cudaGetSymbolAddress((void**)&P,   g_P);

    // 0) round+perm x; round+transpose+perm weights
    roundperm_k<<<1024, 256>>>(x, X, (Bsz * Sq * Dm) / 16);
    {
        dim3 tb(32, 8);
        dim3 gw(Dm / 32, Dm / 32, 1);
        transposeperm_k<<<gw, tb>>>(Wq, WqT, Dm, Dm);
        transposeperm_k<<<gw, tb>>>(Wk, WkT, Dm, Dm);
        transposeperm_k<<<gw, tb>>>(Wv, WvT, Dm, Dm);
    }

    const int M = Bsz * Sq;   // 8192

    // 1) Projections (NT vs transposed weights)
    {
        dim3 grid(Dm / 128, M / 64, 1);
        mma_gemm<false, false, true,  true ><<<grid, 256>>>(X, WqT, Q, Dm, Dm, Dm, Dm, 0, 0, 0);
        mma_gemm<false, false, true,  true ><<<grid, 256>>>(X, WkT, K, Dm, Dm, Dm, Dm, 0, 0, 0);
        mma_gemm<false, false, false, false><<<grid, 256>>>(X, WvT, V, Dm, Dm, Dm, Dm, 0, 0, 0);
    }

    // 2) Scores: S_b = Q_b K_b^T (causal-skip), perm-K output (no round)
    {
        dim3 grid(Sq / 128, Sq / 64, Bsz);
        mma_gemm<true, false, true, false><<<grid, 256>>>(
            Q, K, P, Dm, Dm, Dm, Sq,
            (long)Sq * Dm, (long)Sq * Dm, (long)Sq * Sq);
    }

    // 3) Softmax (in place, causal via perm mapping, tf32-rounded probs)
    softmax_k<<<Bsz * Sq, 256>>>(P);

    // 4) V^T (round+perm), then O = P Vt^T (causal K-limit), normal output
    {
        dim3 tb(32, 8);
        transposeperm_k<<<dim3(Sq / 32, Dm / 32, Bsz), tb>>>(V, Vt, Sq, Dm);
        dim3 grid(Dm / 128, Sq / 64, Bsz);
        mma_gemm<false, true, false, false><<<grid, 256>>>(
            P, Vt, out, Sq, Sq, Sq, Dm,
            (long)Sq * Sq, (long)Sq * Dm, (long)Sq * Dm);
    }

    (void)in_sizes; (void)n_in; (void)out_size;
}

// round 7
// speedup vs baseline: 2.0712x; 2.0712x over previous
#include <cuda_runtime.h>
#include <cuda_fp16.h>
#include <cstdint>

// Problem constants
constexpr int Bsz = 4;
constexpr int Sq  = 2048;
constexpr int Dm  = 1024;

// Scratch (device globals; no allocation allowed).
// "blocked" fp16 layout: matrix [R x K] split into 16x16 blocks, block
// (br,bk) stored at (br*(K/16)+bk)*256 halves; inside a block, 16B chunk
// (g,q), g=0..7,q=0..3 (chunk idx = g*4+q), holds halves
//   x: [row g,   k 2q,2q+1]   y: [row g,   k 2q+8,2q+9]
//   z: [row g+8, k 2q,2q+1]   w: [row g+8, k 2q+8,2q+9]
// One LDS.128 = one full m16n8k16 A-fragment (regs x,z,y,w) or two
// B-fragments (n=g via x,y and n=g+8 via z,w).
__device__ __half g_Xh [(long)Bsz * Sq * Dm];
__device__ __half g_WqT[(long)Dm * Dm];
__device__ __half g_WkT[(long)Dm * Dm];
__device__ __half g_WvT[(long)Dm * Dm];
__device__ __half g_Qh [(long)Bsz * Sq * Dm];
__device__ __half g_Kh [(long)Bsz * Sq * Dm];
__device__ float  g_V  [(long)Bsz * Sq * Dm];   // fp32 row-major (pre-transpose)
__device__ __half g_Vt [(long)Bsz * Sq * Dm];   // V^T per batch, blocked
__device__ float  g_S  [(long)Bsz * Sq * Sq];   // fp32 scores, row-major
__device__ __half g_Ph [(long)Bsz * Sq * Sq];   // fp16 probs, blocked

// ---------------------------------------------------------------------------
// helpers
// ---------------------------------------------------------------------------
__device__ __forceinline__ void cp16(void* s, const void* g) {
    uint32_t sa = (uint32_t)__cvta_generic_to_shared(s);
    asm volatile("cp.async.cg.shared.global [%0], [%1], 16;\n" :: "r"(sa), "l"(g));
}

__device__ __forceinline__ void mma_f16(float* d,
    uint32_t a0, uint32_t a1, uint32_t a2, uint32_t a3,
    uint32_t b0, uint32_t b1) {
    asm volatile(
        "mma.sync.aligned.m16n8k16.row.col.f32.f16.f16.f32 "
        "{%0,%1,%2,%3},{%4,%5,%6,%7},{%8,%9},{%0,%1,%2,%3};"
        : "+f"(d[0]), "+f"(d[1]), "+f"(d[2]), "+f"(d[3])
        : "r"(a0), "r"(a1), "r"(a2), "r"(a3), "r"(b0), "r"(b1));
}

__device__ __forceinline__ uint32_t pack2(float a, float b) {
    __half2 h = __floats2half2_rn(a, b);
    return *(uint32_t*)&h;
}

__device__ __forceinline__ float warp_max(float v) {
    #pragma unroll
    for (int o = 16; o; o >>= 1) v = fmaxf(v, __shfl_xor_sync(0xFFFFFFFFu, v, o));
    return v;
}
__device__ __forceinline__ float warp_sum(float v) {
    #pragma unroll
    for (int o = 16; o; o >>= 1) v += __shfl_xor_sync(0xFFFFFFFFu, v, o);
    return v;
}

// half offset of (r, k) pair start (k even) inside blocked [R x K] matrix
__device__ __forceinline__ long blk_off(int r, int k, int Kd) {
    return ((long)(r >> 4) * (Kd >> 4) + (k >> 4)) * 256
         + ((r & 7) * 4 + ((k >> 1) & 3)) * 8
         + ((r >> 3) & 1) * 4 + ((k >> 3) & 1) * 2;
}

// ---------------------------------------------------------------------------
// Pack fp32 row-major [R x Kd] -> fp16 blocked.  One 16B chunk (8 halves)
// per thread; nchunks = R*Kd/8.
// ---------------------------------------------------------------------------
__global__ void __launch_bounds__(256)
pack_rm(const float* __restrict__ in, __half* __restrict__ out,
        int Kd, long nchunks)
{
    long c = (long)blockIdx.x * blockDim.x + threadIdx.x;
    if (c >= nchunks) return;
    const long blk = c >> 5;
    const int idx = (int)(c & 31);
    const int g = idx >> 2, q = idx & 3;
    const int Kb = Kd >> 4;
    const int rb = (int)(blk / Kb), kb = (int)(blk % Kb);
    const int r = rb * 16 + g, k0 = kb * 16 + q * 2;
    const float* p = in + (long)r * Kd + k0;
    float2 a   = *(const float2*)p;
    float2 b   = *(const float2*)(p + 8);
    float2 clo = *(const float2*)(p + (long)8 * Kd);
    float2 chi = *(const float2*)(p + (long)8 * Kd + 8);
    uint4 u;
    u.x = pack2(a.x, a.y);     u.y = pack2(b.x, b.y);
    u.z = pack2(clo.x, clo.y); u.w = pack2(chi.x, chi.y);
    ((uint4*)out)[c] = u;
}

// ---------------------------------------------------------------------------
// Transpose fp32 [Rin x Cin] (per batch z) -> fp16 blocked [Cin x Rin].
// 32x32 tiles; 128 of the 256 threads each emit one 16B chunk.
// ---------------------------------------------------------------------------
__global__ void __launch_bounds__(256)
pack_t(const float* __restrict__ in, __half* __restrict__ out, int Rin, int Cin)
{
    __shared__ float t[32][33];
    in  += (long)blockIdx.z * Rin * Cin;
    out += (long)blockIdx.z * Rin * Cin;
    const int r0 = blockIdx.x * 32, c0 = blockIdx.y * 32;
    const int x = threadIdx.x, y = threadIdx.y;     // (32, 8)
    #pragma unroll
    for (int i = 0; i < 32; i += 8)
        t[y + i][x] = in[(long)(r0 + y + i) * Cin + c0 + x];
    __syncthreads();

    const int tid = y * 32 + x;
    if (tid < 128) {
        const int blk = tid >> 5, idx = tid & 31;
        const int brl = blk >> 1, bkl = blk & 1;
        const int g = idx >> 2, q = idx & 3;
        const int E  = 16 * brl + g;       // out-row within 32 (orig col)
        const int S0 = 16 * bkl + 2 * q;   // out-k within 32 (orig row)
        uint4 u;
        u.x = pack2(t[S0][E],         t[S0 + 1][E]);
        u.y = pack2(t[S0 + 8][E],     t[S0 + 9][E]);
        u.z = pack2(t[S0][E + 8],     t[S0 + 1][E + 8]);
        u.w = pack2(t[S0 + 8][E + 8], t[S0 + 9][E + 8]);
        const long chunk =
            ((long)((c0 >> 4) + brl) * (Rin >> 4) + (r0 >> 4) + bkl) * 32 + idx;
        ((uint4*)out)[chunk] = u;
    }
}

// ---------------------------------------------------------------------------
// FP16 mma.sync GEMM on blocked operands:  C[M,N] = A[M,K] * B[N,K]^T
// CTA 64(M) x 128(N), 8 warps (2x4), warp 32x32, K-chunk 16, 4-stage cp.async.
// Per warp-chunk: 4 LDS.128 + 8 HMMA.16816.
// EPI_F16: write C into fp16 blocked layout; else fp32 row-major.
// ---------------------------------------------------------------------------
template <bool CAUSAL_SKIP, bool KLIMIT, bool EPI_F16>
__global__ void __launch_bounds__(256)
hgemm(const __half* __restrict__ A, const __half* __restrict__ B, void* Cout,
      int Kd, int ldc, long sA, long sB, long sC)
{
    const int m0 = blockIdx.y * 64;
    const int n0 = blockIdx.x * 128;
    if (CAUSAL_SKIP && n0 > m0 + 63) return;

    A += (long)blockIdx.z * sA;
    B += (long)blockIdx.z * sB;

    const int Keff = KLIMIT ? min(Kd, m0 + 64) : Kd;
    const int nkt  = Keff >> 4;
    const int Kb   = Kd >> 4;

    __shared__ uint4 sm[4][384];   // per stage: A chunks [0,128), B [128,384)

    const int tid  = threadIdx.x;
    const int warp = tid >> 5;
    const int lane = tid & 31;
    const int wm   = warp >> 2;    // 0..1
    const int wn   = warp & 3;     // 0..3

    const uint4* ag = (const uint4*)A
        + ((long)((m0 >> 4) + (warp & 3)) * Kb) * 32 + lane;
    const uint4* bg = (const uint4*)B
        + ((long)((n0 >> 4) + warp) * Kb) * 32 + lane;

    auto load_stage = [&](int st, int kt) {
        if (tid < 128) cp16(&sm[st][tid], ag + kt * 32);
        cp16(&sm[st][128 + tid], bg + kt * 32);
    };

    #pragma unroll
    for (int s = 0; s < 3; s++) {
        if (s < nkt) load_stage(s, s);
        asm volatile("cp.async.commit_group;\n");
    }

    float acc[2][4][4] = {};

    for (int kt = 0; kt < nkt; ++kt) {
        const int cur = kt & 3;
        asm volatile("cp.async.wait_group 2;\n");
        __syncthreads();

        if (kt + 3 < nkt) load_stage((kt + 3) & 3, kt + 3);
        asm volatile("cp.async.commit_group;\n");

        uint4 Aq[2], Bq[2];
        #pragma unroll
        for (int mi = 0; mi < 2; mi++)
            Aq[mi] = sm[cur][(wm * 2 + mi) * 32 + lane];
        #pragma unroll
        for (int nj = 0; nj < 2; nj++)
            Bq[nj] = sm[cur][128 + (wn * 2 + nj) * 32 + lane];

        #pragma unroll
        for (int mi = 0; mi < 2; mi++) {
            mma_f16(acc[mi][0], Aq[mi].x, Aq[mi].z, Aq[mi].y, Aq[mi].w, Bq[0].x, Bq[0].y);
            mma_f16(acc[mi][1], Aq[mi].x, Aq[mi].z, Aq[mi].y, Aq[mi].w, Bq[0].z, Bq[0].w);
            mma_f16(acc[mi][2], Aq[mi].x, Aq[mi].z, Aq[mi].y, Aq[mi].w, Bq[1].x, Bq[1].y);
            mma_f16(acc[mi][3], Aq[mi].x, Aq[mi].z, Aq[mi].y, Aq[mi].w, Bq[1].z, Bq[1].w);
        }
        __syncthreads();
    }

    // Epilogue
    if (EPI_F16) {
        __half* Ch = (__half*)Cout;   // blocked layout, no batch (proj only)
        #pragma unroll
        for (int mi = 0; mi < 2; mi++) {
            #pragma unroll
            for (int nt = 0; nt < 4; nt++) {
                const int r0 = m0 + wm * 32 + mi * 16 + (lane >> 2);
                const int c0 = n0 + wn * 32 + nt * 8 + 2 * (lane & 3);
                const long off = blk_off(r0, c0, ldc);
                *(uint32_t*)(Ch + off)     = pack2(acc[mi][nt][0], acc[mi][nt][1]);
                *(uint32_t*)(Ch + off + 4) = pack2(acc[mi][nt][2], acc[mi][nt][3]);
            }
        }
    } else {
        float* Cf = (float*)Cout + (long)blockIdx.z * sC;
        #pragma unroll
        for (int mi = 0; mi < 2; mi++) {
            #pragma unroll
            for (int nt = 0; nt < 4; nt++) {
                const int r0 = m0 + wm * 32 + mi * 16 + (lane >> 2);
                const int c0 = n0 + wn * 32 + nt * 8 + 2 * (lane & 3);
                *(float2*)&Cf[(long)r0 * ldc + c0] =
                    make_float2(acc[mi][nt][0], acc[mi][nt][1]);
                *(float2*)&Cf[(long)(r0 + 8) * ldc + c0] =
                    make_float2(acc[mi][nt][2], acc[mi][nt][3]);
            }
        }
    }
}

// ---------------------------------------------------------------------------
// Causal row softmax: fp32 scores (row-major) -> fp16 probs (blocked).
// Logits s/32.  Zero-fills [len, ceil64(len)) so the PV GEMM (Keff=m0+64)
// reads only valid data.
// ---------------------------------------------------------------------------
__global__ void __launch_bounds__(256)
softmax_k(const float* __restrict__ S, __half* __restrict__ Ph)
{
    const int row = blockIdx.x;
    const int b = row >> 11;
    const int i = row & 2047;
    const float* p = S + ((long)b * Sq + i) * Sq;
    __half* ph = Ph + (long)b * Sq * Sq;
    const int tid = threadIdx.x;
    const int len = i + 1;
    const int lenPad = (len + 63) & ~63;
    const int npairs = lenPad >> 1;

    float e[4][2];
    #pragma unroll
    for (int k = 0; k < 4; k++) {
        const int j2 = tid + 256 * k;
        if (j2 < npairs) {
            const float2 v = *(const float2*)(p + 2 * j2);
            const int j = 2 * j2;
            e[k][0] = (j     < len) ? v.x : -3.4e38f;
            e[k][1] = (j + 1 < len) ? v.y : -3.4e38f;
        } else {
            e[k][0] = e[k][1] = -3.4e38f;
        }
    }

    float mx = -3.4e38f;
    #pragma unroll
    for (int k = 0; k < 4; k++) mx = fmaxf(mx, fmaxf(e[k][0], e[k][1]));
    mx = warp_max(mx);

    __shared__ float red[8];
    if ((tid & 31) == 0) red[tid >> 5] = mx;
    __syncthreads();
    mx = red[0];
    #pragma unroll
    for (int w = 1; w < 8; w++) mx = fmaxf(mx, red[w]);

    float s = 0.f;
    #pragma unroll
    for (int k = 0; k < 4; k++) {
        e[k][0] = __expf((e[k][0] - mx) * 0.03125f);
        e[k][1] = __expf((e[k][1] - mx) * 0.03125f);
        s += e[k][0] + e[k][1];
    }
    s = warp_sum(s);
    __syncthreads();
    if ((tid & 31) == 0) red[tid >> 5] = s;
    __syncthreads();
    float tot = 0.f;
    #pragma unroll
    for (int w = 0; w < 8; w++) tot += red[w];
    const float inv = 1.0f / tot;

    #pragma unroll
    for (int k = 0; k < 4; k++) {
        const int j2 = tid + 256 * k;
        if (j2 < npairs) {
            const int j = 2 * j2;
            *(uint32_t*)(ph + blk_off(i, j, Sq)) =
                pack2(e[k][0] * inv, e[k][1] * inv);
        }
    }
}

// ---------------------------------------------------------------------------
extern "C" void kernel_launch(void* const* d_in, const int* in_sizes, int n_in,
                              void* d_out, int out_size)
{
    const float* x  = (const float*)d_in[0];
    const float* Wq = (const float*)d_in[1];
    const float* Wk = (const float*)d_in[2];
    const float* Wv = (const float*)d_in[3];
    float* out = (float*)d_out;

    __half *Xh, *WqT, *WkT, *WvT, *Qh, *Kh, *Vt, *Ph;
    float *V, *Sb;
    cudaGetSymbolAddress((void**)&Xh,  g_Xh);
    cudaGetSymbolAddress((void**)&WqT, g_WqT);
    cudaGetSymbolAddress((void**)&WkT, g_WkT);
    cudaGetSymbolAddress((void**)&WvT, g_WvT);
    cudaGetSymbolAddress((void**)&Qh,  g_Qh);
    cudaGetSymbolAddress((void**)&Kh,  g_Kh);
    cudaGetSymbolAddress((void**)&V,   g_V);
    cudaGetSymbolAddress((void**)&Vt,  g_Vt);
    cudaGetSymbolAddress((void**)&Sb,  g_S);
    cudaGetSymbolAddress((void**)&Ph,  g_Ph);

    const int M = Bsz * Sq;   // 8192

    // 0) pack x (row-major fp32 -> blocked fp16); pack W^T (transpose+blocked)
    {
        const long nchunks = (long)M * Dm / 8;    // 16B chunks (8 halves each)
        pack_rm<<<(int)((nchunks + 255) / 256), 256>>>(x, Xh, Dm, nchunks);
        dim3 tb(32, 8);
        dim3 gw(Dm / 32, Dm / 32, 1);
        pack_t<<<gw, tb>>>(Wq, WqT, Dm, Dm);
        pack_t<<<gw, tb>>>(Wk, WkT, Dm, Dm);
        pack_t<<<gw, tb>>>(Wv, WvT, Dm, Dm);
    }

    // 1) Projections: Q,K -> fp16 blocked directly; V -> fp32 row-major
    {
        dim3 grid(Dm / 128, M / 64, 1);
        hgemm<false, false, true ><<<grid, 256>>>(Xh, WqT, Qh, Dm, Dm, 0, 0, 0);
        hgemm<false, false, true ><<<grid, 256>>>(Xh, WkT, Kh, Dm, Dm, 0, 0, 0);
        hgemm<false, false, false><<<grid, 256>>>(Xh, WvT, V,  Dm, Dm, 0, 0, 0);
    }

    // 2) Scores: S_b = Q_b K_b^T (causal-skip), fp32 row-major out
    {
        dim3 grid(Sq / 128, Sq / 64, Bsz);
        hgemm<true, false, false><<<grid, 256>>>(
            Qh, Kh, Sb, Dm, Sq,
            (long)Sq * Dm, (long)Sq * Dm, (long)Sq * Sq);
    }

    // 3) Softmax -> fp16 blocked probs
    softmax_k<<<Bsz * Sq, 256>>>(Sb, Ph);

    // 4) V^T pack, then O = P Vt^T (causal K-limit), fp32 out
    {
        dim3 tb(32, 8);
        pack_t<<<dim3(Sq / 32, Dm / 32, Bsz), tb>>>(V, Vt, Sq, Dm);
        dim3 grid(Dm / 128, Sq / 64, Bsz);
        hgemm<false, true, false><<<grid, 256>>>(
            Ph, Vt, out, Sq, Dm,
            (long)Sq * Sq, (long)Sq * Dm, (long)Sq * Dm);
    }

    (void)in_sizes; (void)n_in; (void)out_size;
}